// round 1
// baseline (speedup 1.0000x reference)
#include <cuda_runtime.h>
#include <cstddef>

// Problem constants (fixed by the dataset: K=64, N=1048576, NS=1024)
constexpr int   Kdim  = 64;
constexpr long  Nn    = 1048576;
constexpr int   NSs   = 1024;
constexpr int   Bseq  = 1024;       // Nn / NSs
constexpr int   WARPS = 8;          // warps (=sequences) per CTA
constexpr int   CTAS  = Bseq / WARPS;
constexpr int   TBLK  = 32;         // emission staging block (time steps)
constexpr int   LPSTRIDE = TBLK + 1; // pad to 33 floats -> conflict-free LDS
constexpr float L2E   = 1.4426950408889634f;
constexpr float LN2   = 0.6931471805599453f;

// scratch (no allocations allowed)
__device__ float gTp[Kdim * Kdim];   // row-softmax of T (probabilities)
__device__ float gLpi2[Kdim];        // log_softmax(pi) * log2(e)
__device__ float gPart[Bseq];        // per-sequence results

// ---------------------------------------------------------------------------
// small helpers
// ---------------------------------------------------------------------------
__device__ __forceinline__ float ex2f(float x) {
    float r; asm("ex2.approx.ftz.f32 %0, %1;" : "=f"(r) : "f"(x)); return r;
}
__device__ __forceinline__ float lg2f(float x) {
    float r; asm("lg2.approx.ftz.f32 %0, %1;" : "=f"(r) : "f"(x)); return r;
}
__device__ __forceinline__ float warp_sum(float v) {
#pragma unroll
    for (int o = 16; o > 0; o >>= 1)
        v += __shfl_xor_sync(0xffffffffu, v, o);
    return v;
}

// Stage 64 rows x 32 time-steps of emissions into shared (coalesced LDG.128).
// base = log_pdf + b*NS + t0 ; row k is at base + k*Nn.
__device__ __forceinline__ void stage(float* lpS, const float* __restrict__ base, int l) {
#pragma unroll
    for (int i = 0; i < 16; i++) {
        int m   = (i << 5) + l;        // 0..511
        int row = m >> 3;              // 0..63
        int c4  = (m & 7) << 2;        // 0,4,...,28
        const float4 v = *reinterpret_cast<const float4*>(base + (size_t)row * Nn + c4);
        float* d = lpS + row * LPSTRIDE + c4;
        d[0] = v.x; d[1] = v.y; d[2] = v.z; d[3] = v.w;
    }
}

// ---------------------------------------------------------------------------
// precompute: T_prob = softmax(T, rows);  gLpi2 = log_softmax(pi)*log2e
// ---------------------------------------------------------------------------
__global__ void prep_kernel(const float* __restrict__ pi, const float* __restrict__ T) {
    int j = threadIdx.x;  // 64 threads, one row each
    // softmax of row j of T
    float m = -1e30f;
    for (int k = 0; k < Kdim; k++) m = fmaxf(m, T[j * Kdim + k]);
    float s = 0.f;
    for (int k = 0; k < Kdim; k++) s += expf(T[j * Kdim + k] - m);
    float inv = 1.f / s;
    for (int k = 0; k < Kdim; k++) gTp[j * Kdim + k] = expf(T[j * Kdim + k] - m) * inv;
    // log_softmax(pi) (redundant per-thread reduction is fine at this size)
    float mp = -1e30f;
    for (int k = 0; k < Kdim; k++) mp = fmaxf(mp, pi[k]);
    float sp = 0.f;
    for (int k = 0; k < Kdim; k++) sp += expf(pi[k] - mp);
    gLpi2[j] = (pi[j] - mp - logf(sp)) * L2E;
}

// ---------------------------------------------------------------------------
// main forward scan: one warp per sequence
// ---------------------------------------------------------------------------
__global__ void __launch_bounds__(WARPS * 32, 1)
fwd_kernel(const float* __restrict__ lp) {
    extern __shared__ float sm[];
    const int warp = threadIdx.x >> 5;
    const int l    = threadIdx.x & 31;
    const int b    = blockIdx.x * WARPS + warp;

    float*  lpS = sm + warp * (Kdim * LPSTRIDE);
    float2* qS  = reinterpret_cast<float2*>(sm + WARPS * Kdim * LPSTRIDE) + (warp << 6);

    // --- load T columns l and l+32 into packed f32x2 registers (128 regs) ---
    unsigned long long Tr[Kdim];
#pragma unroll
    for (int j = 0; j < Kdim; j++) {
        float a = gTp[j * Kdim + l];
        float c = gTp[j * Kdim + l + 32];
        asm("mov.b64 %0, {%1,%2};" : "=l"(Tr[j]) : "f"(a), "f"(c));
    }
    const float lpiA = gLpi2[l];
    const float lpiB = gLpi2[l + 32];

    const float* base = lp + (size_t)b * NSs;

    // --- stage first emission block & initialize alpha0 = lp0 + log_pi ---
    stage(lpS, base, l);
    __syncwarp();

    float eA = lpS[l * LPSTRIDE];
    float eB = lpS[(l + 32) * LPSTRIDE];
    float qA = ex2f(fmaf(eA, L2E, lpiA));
    float qB = ex2f(fmaf(eB, L2E, lpiB));
    float S  = warp_sum(qA + qB);
    qS[l]      = make_float2(qA, qA);
    qS[l + 32] = make_float2(qB, qB);
    __syncwarp();

    float cacc = 0.f;

    for (int t = 1; t < NSs; t++) {
        if ((t & (TBLK - 1)) == 0) {
            stage(lpS, base + t, l);
            __syncwarp();
        }
        float g = lg2f(S);   // log2 of previous total mass
        cacc += g;

        const int tt = t & (TBLK - 1);
        eA = lpS[l * LPSTRIDE + tt];
        eB = lpS[(l + 32) * LPSTRIDE + tt];

        // d = q^T * T_prob  for columns (l, l+32), packed f32x2
        unsigned long long a0 = 0ull, a1 = 0ull;
#pragma unroll
        for (int j = 0; j < Kdim; j += 2) {
            ulonglong2 w = *reinterpret_cast<const ulonglong2*>(qS + j); // (q_j,q_j),(q_j+1,q_j+1)
            asm("fma.rn.f32x2 %0, %1, %2, %0;" : "+l"(a0) : "l"(w.x), "l"(Tr[j]));
            asm("fma.rn.f32x2 %0, %1, %2, %0;" : "+l"(a1) : "l"(w.y), "l"(Tr[j + 1]));
        }
        unsigned long long dsum;
        asm("add.rn.f32x2 %0, %1, %2;" : "=l"(dsum) : "l"(a0), "l"(a1));
        float2 d = *reinterpret_cast<float2*>(&dsum);

        // q' = exp2(e*log2e - g) * d   (renormalized by previous mass)
        qA = ex2f(fmaf(eA, L2E, -g)) * d.x;
        qB = ex2f(fmaf(eB, L2E, -g)) * d.y;

        S = warp_sum(qA + qB);
        qS[l]      = make_float2(qA, qA);
        qS[l + 32] = make_float2(qB, qB);
        __syncwarp();
    }

    if (l == 0) gPart[b] = LN2 * (cacc + lg2f(S));
}

// ---------------------------------------------------------------------------
// deterministic final reduction of 1024 per-sequence results
// ---------------------------------------------------------------------------
__global__ void reduce_kernel(float* __restrict__ out) {
    __shared__ double s[256];
    int t = threadIdx.x;
    double v = 0.0;
    for (int i = t; i < Bseq; i += 256) v += (double)gPart[i];
    s[t] = v;
    __syncthreads();
    for (int o = 128; o > 0; o >>= 1) {
        if (t < o) s[t] += s[t + o];
        __syncthreads();
    }
    if (t == 0) out[0] = (float)s[0];
}

// ---------------------------------------------------------------------------
extern "C" void kernel_launch(void* const* d_in, const int* in_sizes, int n_in,
                              void* d_out, int out_size) {
    const float* lp = (const float*)d_in[0];  // log_pdf (K, N)
    const float* pi = (const float*)d_in[1];  // pi (K,)
    const float* T  = (const float*)d_in[2];  // T (K, K)
    (void)in_sizes; (void)n_in; (void)out_size;

    const int smem = WARPS * Kdim * LPSTRIDE * 4 + WARPS * Kdim * 8;  // 71680 B
    cudaFuncSetAttribute(fwd_kernel, cudaFuncAttributeMaxDynamicSharedMemorySize, smem);

    prep_kernel<<<1, Kdim>>>(pi, T);
    fwd_kernel<<<CTAS, WARPS * 32, smem>>>(lp);
    reduce_kernel<<<1, 256>>>((float*)d_out);
}

// round 2
// speedup vs baseline: 1.6055x; 1.6055x over previous
#include <cuda_runtime.h>
#include <cstddef>

// Fixed problem shape: K=64, N=1048576, NS=1024, B=1024
constexpr int   Kdim   = 64;
constexpr long  Nn     = 1048576;
constexpr int   NSs    = 1024;
constexpr int   Bseq   = 1024;
constexpr int   STRIDE = 36;    // staging row stride in floats (16B-aligned for cp.async)
constexpr float L2E    = 1.4426950408889634f;
constexpr float LN2    = 0.6931471805599453f;

__device__ float gTp[Kdim * Kdim];   // row-softmax of T
__device__ float gLpi2[Kdim];        // log_softmax(pi) * log2(e)
__device__ float gPart[Bseq];        // per-sequence log-likelihoods

// ---------------------------------------------------------------------------
// helpers
// ---------------------------------------------------------------------------
__device__ __forceinline__ float ex2f(float x) {
    float r; asm("ex2.approx.ftz.f32 %0, %1;" : "=f"(r) : "f"(x)); return r;
}
__device__ __forceinline__ float lg2f(float x) {
    float r; asm("lg2.approx.ftz.f32 %0, %1;" : "=f"(r) : "f"(x)); return r;
}
__device__ __forceinline__ float warp_sum(float v) {
#pragma unroll
    for (int o = 16; o > 0; o >>= 1) v += __shfl_xor_sync(0xffffffffu, v, o);
    return v;
}
__device__ __forceinline__ void fma2(unsigned long long& acc,
                                     unsigned long long a, unsigned long long b) {
    asm("fma.rn.f32x2 %0, %1, %2, %0;" : "+l"(acc) : "l"(a), "l"(b));
}
__device__ __forceinline__ unsigned long long mul2(unsigned long long a, unsigned long long b) {
    unsigned long long r; asm("mul.rn.f32x2 %0, %1, %2;" : "=l"(r) : "l"(a), "l"(b)); return r;
}
__device__ __forceinline__ unsigned long long add2(unsigned long long a, unsigned long long b) {
    unsigned long long r; asm("add.rn.f32x2 %0, %1, %2;" : "=l"(r) : "l"(a), "l"(b)); return r;
}
__device__ __forceinline__ float2 unpack2(unsigned long long v) {
    float2 r; asm("mov.b64 {%0,%1}, %2;" : "=f"(r.x), "=f"(r.y) : "l"(v)); return r;
}
__device__ __forceinline__ unsigned long long pack2(float a, float b) {
    unsigned long long r; asm("mov.b64 %0, {%1,%2};" : "=l"(r) : "f"(a), "f"(b)); return r;
}
__device__ __forceinline__ void cpasync16(void* dst, const void* src) {
    unsigned d = (unsigned)__cvta_generic_to_shared(dst);
    asm volatile("cp.async.ca.shared.global [%0], [%1], 16;" :: "r"(d), "l"(src));
}
template <int N> __device__ __forceinline__ void wait_group() {
    asm volatile("cp.async.wait_group %0;" :: "n"(N));
}
__device__ __forceinline__ void commit_group() {
    asm volatile("cp.async.commit_group;");
}

// issue one 32-step emission block (64 rows x 32 floats) into staging buffer
__device__ __forceinline__ void issue_stage(float* sbuf, const float* gbase, int l) {
#pragma unroll
    for (int i = 0; i < 16; i++) {
        int c   = (i << 5) + l;
        int row = c >> 3;
        int c4  = (c & 7) << 2;
        cpasync16(sbuf + row * STRIDE + c4, gbase + (size_t)row * Nn + c4);
    }
    commit_group();
}

// ---------------------------------------------------------------------------
// prep: gTp = softmax(T, rows); gLpi2 = log_softmax(pi)*log2e  (warp-parallel)
// ---------------------------------------------------------------------------
__global__ void prep_kernel(const float* __restrict__ pi, const float* __restrict__ T) {
    int w = threadIdx.x >> 5, l = threadIdx.x & 31;
    int row = blockIdx.x * 32 + w;
    float a = T[row * Kdim + l], c = T[row * Kdim + l + 32];
    float m = fmaxf(a, c);
#pragma unroll
    for (int o = 16; o > 0; o >>= 1) m = fmaxf(m, __shfl_xor_sync(0xffffffffu, m, o));
    float ea = expf(a - m), ec = expf(c - m);
    float s = warp_sum(ea + ec);
    float inv = 1.0f / s;
    gTp[row * Kdim + l]      = ea * inv;
    gTp[row * Kdim + l + 32] = ec * inv;

    if (blockIdx.x == 0 && w == 0) {
        float pa = pi[l], pb = pi[l + 32];
        float m2 = fmaxf(pa, pb);
#pragma unroll
        for (int o = 16; o > 0; o >>= 1) m2 = fmaxf(m2, __shfl_xor_sync(0xffffffffu, m2, o));
        float sp = warp_sum(expf(pa - m2) + expf(pb - m2));
        float ls = logf(sp);
        gLpi2[l]      = (pa - m2 - ls) * L2E;
        gLpi2[l + 32] = (pb - m2 - ls) * L2E;
    }
}

// ---------------------------------------------------------------------------
// one forward step: d = q^T * Tp (both columns l, l+32), q' = f * d
// ---------------------------------------------------------------------------
__device__ __forceinline__ void step(const float* qR, float* qW, int l,
                                     const unsigned long long* Trl,
                                     const unsigned long long* Trh,
                                     float eA, float eB, float gp,
                                     float& qA, float& qB) {
    __syncwarp();
    const ulonglong2* qp = (const ulonglong2*)qR;
    ulonglong2 w0 = qp[0];
    unsigned long long aA0 = mul2(w0.x, Trl[0]);
    unsigned long long aA1 = mul2(w0.y, Trl[1]);
    unsigned long long aB0 = mul2(w0.x, Trh[0]);
    unsigned long long aB1 = mul2(w0.y, Trh[1]);
#pragma unroll
    for (int i = 1; i < 16; i++) {
        ulonglong2 w = qp[i];
        fma2(aA0, w.x, Trl[2 * i]);     fma2(aA1, w.y, Trl[2 * i + 1]);
        fma2(aB0, w.x, Trh[2 * i]);     fma2(aB1, w.y, Trh[2 * i + 1]);
    }
    float2 dA = unpack2(add2(aA0, aA1));
    float2 dB = unpack2(add2(aB0, aB1));
    float fA = ex2f(fmaf(eA, L2E, gp));
    float fB = ex2f(fmaf(eB, L2E, gp));
    qA = fA * (dA.x + dA.y);
    qB = fB * (dB.x + dB.y);
    qW[l]      = qA;
    qW[l + 32] = qB;
}

// ---------------------------------------------------------------------------
// forward scan: one single-warp CTA per sequence (1024 CTAs, ~7 warps/SM)
// ---------------------------------------------------------------------------
__global__ void __launch_bounds__(32) fwd_kernel(const float* __restrict__ lp) {
    __shared__ float st[2][Kdim * STRIDE];
    __shared__ float q0[Kdim], q1[Kdim];
    const int l = threadIdx.x;
    const int b = blockIdx.x;
    const float* base = lp + (size_t)b * NSs;

    issue_stage(st[0], base, l);
    issue_stage(st[1], base + 32, l);

    // T columns l and l+32, packed as row-pairs: Trl[p]=(Tp[2p][l],Tp[2p+1][l])
    unsigned long long Trl[32], Trh[32];
#pragma unroll
    for (int p = 0; p < 32; p++) {
        Trl[p] = pack2(gTp[(2 * p) * Kdim + l],      gTp[(2 * p + 1) * Kdim + l]);
        Trh[p] = pack2(gTp[(2 * p) * Kdim + l + 32], gTp[(2 * p + 1) * Kdim + l + 32]);
    }
    const float lpiA = gLpi2[l];
    const float lpiB = gLpi2[l + 32];

    wait_group<1>();   // block 0 arrived (block 1 may still be in flight)
    __syncwarp();

    // t = 0: alpha0 = lp0 + log_pi  (in scaled-prob domain)
    float4 e4A = *(const float4*)(st[0] + l * STRIDE);
    float4 e4B = *(const float4*)(st[0] + (l + 32) * STRIDE);
    float qA = ex2f(fmaf(e4A.x, L2E, lpiA));
    float qB = ex2f(fmaf(e4B.x, L2E, lpiB));
    q0[l]      = qA;
    q0[l + 32] = qB;

    double cacc = 0.0;
    float  gp   = 0.0f;   // pending -log2(scale), folded into next exp

    // t = 1, 2, 3
    step(q0, q1, l, Trl, Trh, e4A.y, e4B.y, 0.f, qA, qB);
    step(q1, q0, l, Trl, Trh, e4A.z, e4B.z, 0.f, qA, qB);
    step(q0, q1, l, Trl, Trh, e4A.w, e4B.w, 0.f, qA, qB);

#pragma unroll 1
    for (int t0 = 4; t0 < NSs; t0 += 4) {
        if ((t0 & 31) == 0) {                      // 32-step block boundary
            wait_group<0>();
            __syncwarp();
            if (t0 + 32 < NSs)
                issue_stage(st[((t0 >> 5) + 1) & 1], base + t0 + 32, l);
        }
        const float* sb = st[(t0 >> 5) & 1];
        const int tt = t0 & 31;
        float4 eA = *(const float4*)(sb + l * STRIDE + tt);
        float4 eB = *(const float4*)(sb + (l + 32) * STRIDE + tt);

        step(q1, q0, l, Trl, Trh, eA.x, eB.x, gp,  qA, qB);
        step(q0, q1, l, Trl, Trh, eA.y, eB.y, 0.f, qA, qB);
        step(q1, q0, l, Trl, Trh, eA.z, eB.z, 0.f, qA, qB);
        step(q0, q1, l, Trl, Trh, eA.w, eB.w, 0.f, qA, qB);
        gp = 0.0f;

        if ((t0 & 15) == 4) {                      // renorm every 16 steps (off-chain)
            float S = warp_sum(qA + qB);
            float g = lg2f(S);
            cacc += (double)g;
            gp = -g;                                // applied via next step's ex2 arg
        }
    }

    float S = warp_sum(qA + qB);
    if (l == 0) gPart[b] = LN2 * (float)(cacc + (double)lg2f(S));
}

// ---------------------------------------------------------------------------
// deterministic final reduction
// ---------------------------------------------------------------------------
__global__ void reduce_kernel(float* __restrict__ out) {
    __shared__ double s[256];
    int t = threadIdx.x;
    double v = 0.0;
    for (int i = t; i < Bseq; i += 256) v += (double)gPart[i];
    s[t] = v;
    __syncthreads();
    for (int o = 128; o > 0; o >>= 1) {
        if (t < o) s[t] += s[t + o];
        __syncthreads();
    }
    if (t == 0) out[0] = (float)s[0];
}

// ---------------------------------------------------------------------------
extern "C" void kernel_launch(void* const* d_in, const int* in_sizes, int n_in,
                              void* d_out, int out_size) {
    const float* lp = (const float*)d_in[0];  // log_pdf (K, N)
    const float* pi = (const float*)d_in[1];  // pi (K,)
    const float* T  = (const float*)d_in[2];  // T (K, K)
    (void)in_sizes; (void)n_in; (void)out_size;

    prep_kernel<<<2, 1024>>>(pi, T);
    fwd_kernel<<<Bseq, 32>>>(lp);
    reduce_kernel<<<1, 256>>>((float*)d_out);
}

// round 3
// speedup vs baseline: 1.8562x; 1.1561x over previous
#include <cuda_runtime.h>
#include <cstddef>

// Fixed problem shape: K=64, N=1048576, NS=1024, B=1024
constexpr int   Kdim   = 64;
constexpr long  Nn     = 1048576;
constexpr int   NSs    = 1024;
constexpr int   Bseq   = 1024;
constexpr int   STRIDE = 36;    // staging row stride (floats); 144B keeps cp.async.16 aligned
constexpr float L2E    = 1.4426950408889634f;
constexpr float LN2    = 0.6931471805599453f;

__device__ float    gTp[Kdim * Kdim];    // row-softmax of T (fp32)
__device__ unsigned gT2[Kdim * 32];      // gT2[k*32+j] = bf16x2(Tp[2j][k], Tp[2j+1][k])
__device__ float    gLpi2[Kdim];         // log_softmax(pi) * log2(e)
__device__ float    gPart[Bseq];

// ---------------------------------------------------------------------------
// helpers
// ---------------------------------------------------------------------------
__device__ __forceinline__ float ex2f(float x) {
    float r; asm("ex2.approx.ftz.f32 %0, %1;" : "=f"(r) : "f"(x)); return r;
}
__device__ __forceinline__ float lg2f(float x) {
    float r; asm("lg2.approx.ftz.f32 %0, %1;" : "=f"(r) : "f"(x)); return r;
}
__device__ __forceinline__ float warp_sum(float v) {
#pragma unroll
    for (int o = 16; o > 0; o >>= 1) v += __shfl_xor_sync(0xffffffffu, v, o);
    return v;
}
__device__ __forceinline__ void hfma2(unsigned& acc, unsigned a, unsigned b) {
    asm("fma.rn.bf16x2 %0, %1, %2, %0;" : "+r"(acc) : "r"(a), "r"(b));
}
__device__ __forceinline__ unsigned hadd2(unsigned a, unsigned b) {
    unsigned r; asm("add.rn.bf16x2 %0, %1, %2;" : "=r"(r) : "r"(a), "r"(b)); return r;
}
__device__ __forceinline__ unsigned pack_bf16x2(float lo, float hi) {
    unsigned r; asm("cvt.rn.bf16x2.f32 %0, %1, %2;" : "=r"(r) : "f"(hi), "f"(lo)); return r;
}
__device__ __forceinline__ void cpasync16(void* dst, const void* src) {
    unsigned d = (unsigned)__cvta_generic_to_shared(dst);
    asm volatile("cp.async.ca.shared.global [%0], [%1], 16;" :: "r"(d), "l"(src));
}
template <int N> __device__ __forceinline__ void wait_group() {
    asm volatile("cp.async.wait_group %0;" :: "n"(N));
}
__device__ __forceinline__ void commit_group() {
    asm volatile("cp.async.commit_group;");
}

// issue one 32-step emission block (64 rows x 32 floats) into staging buffer
__device__ __forceinline__ void issue_stage(float* sbuf, const float* gbase, int l) {
#pragma unroll
    for (int i = 0; i < 16; i++) {
        int c   = (i << 5) + l;
        int row = c >> 3;
        int c4  = (c & 7) << 2;
        cpasync16(sbuf + row * STRIDE + c4, gbase + (size_t)row * Nn + c4);
    }
    commit_group();
}

// ---------------------------------------------------------------------------
// prep: gTp = softmax(T, rows); gLpi2 = log_softmax(pi)*log2e
// ---------------------------------------------------------------------------
__global__ void prep_kernel(const float* __restrict__ pi, const float* __restrict__ T) {
    int w = threadIdx.x >> 5, l = threadIdx.x & 31;
    int row = blockIdx.x * 32 + w;
    float a = T[row * Kdim + l], c = T[row * Kdim + l + 32];
    float m = fmaxf(a, c);
#pragma unroll
    for (int o = 16; o > 0; o >>= 1) m = fmaxf(m, __shfl_xor_sync(0xffffffffu, m, o));
    float ea = expf(a - m), ec = expf(c - m);
    float s = warp_sum(ea + ec);
    float inv = 1.0f / s;
    gTp[row * Kdim + l]      = ea * inv;
    gTp[row * Kdim + l + 32] = ec * inv;

    if (blockIdx.x == 0 && w == 0) {
        float pa = pi[l], pb = pi[l + 32];
        float m2 = fmaxf(pa, pb);
#pragma unroll
        for (int o = 16; o > 0; o >>= 1) m2 = fmaxf(m2, __shfl_xor_sync(0xffffffffu, m2, o));
        float sp = warp_sum(expf(pa - m2) + expf(pb - m2));
        float ls = logf(sp);
        gLpi2[l]      = (pa - m2 - ls) * L2E;
        gLpi2[l + 32] = (pb - m2 - ls) * L2E;
    }
}

// pack T columns as bf16x2 row-pairs: gT2[k][j] = (Tp[2j][k], Tp[2j+1][k])
__global__ void pack_kernel() {
    int k = blockIdx.x, j = threadIdx.x;   // 64 blocks x 32 threads
    gT2[k * 32 + j] = pack_bf16x2(gTp[(2 * j) * Kdim + k], gTp[(2 * j + 1) * Kdim + k]);
}

// ---------------------------------------------------------------------------
// one forward step, bf16 matvec.
// lane l owns states (2l, 2l+1). qR/qW: 32 bf16x2 words (states 2j,2j+1).
// ---------------------------------------------------------------------------
__device__ __forceinline__ void step(const unsigned* qR, unsigned* qW, int l,
                                     const unsigned* Ta, const unsigned* Tb,
                                     float eA, float eB, float gp,
                                     float& qAf, float& qBf) {
    __syncwarp();
    const uint4* qp = (const uint4*)qR;
    unsigned a0 = 0u, a1 = 0u, b0 = 0u, b1 = 0u;
#pragma unroll
    for (int i = 0; i < 8; i++) {
        uint4 w = qp[i];
        hfma2(a0, w.x, Ta[4 * i + 0]);  hfma2(b0, w.x, Tb[4 * i + 0]);
        hfma2(a1, w.y, Ta[4 * i + 1]);  hfma2(b1, w.y, Tb[4 * i + 1]);
        hfma2(a0, w.z, Ta[4 * i + 2]);  hfma2(b0, w.z, Tb[4 * i + 2]);
        hfma2(a1, w.w, Ta[4 * i + 3]);  hfma2(b1, w.w, Tb[4 * i + 3]);
    }
    unsigned a = hadd2(a0, a1), b = hadd2(b0, b1);
    float dA = __uint_as_float(a << 16) + __uint_as_float(a & 0xffff0000u);
    float dB = __uint_as_float(b << 16) + __uint_as_float(b & 0xffff0000u);
    float fA = ex2f(fmaf(eA, L2E, gp));
    float fB = ex2f(fmaf(eB, L2E, gp));
    qAf = fA * dA;
    qBf = fB * dB;
    qW[l] = pack_bf16x2(qAf, qBf);
}

// ---------------------------------------------------------------------------
// forward scan: one single-warp CTA per sequence
// ---------------------------------------------------------------------------
__global__ void __launch_bounds__(32) fwd_kernel(const float* __restrict__ lp) {
    __shared__ float    st[2][Kdim * STRIDE];
    __shared__ unsigned q0[32], q1[32];
    const int l = threadIdx.x;
    const int b = blockIdx.x;
    const float* base = lp + (size_t)b * NSs;

    issue_stage(st[0], base, l);
    issue_stage(st[1], base + 32, l);

    // T columns 2l and 2l+1, packed over row-pairs
    unsigned Ta[32], Tb[32];
#pragma unroll
    for (int j = 0; j < 32; j++) {
        Ta[j] = gT2[(2 * l) * 32 + j];
        Tb[j] = gT2[(2 * l + 1) * 32 + j];
    }
    const float lpiA = gLpi2[2 * l];
    const float lpiB = gLpi2[2 * l + 1];

    wait_group<1>();
    __syncwarp();

    // t = 0: q0 = exp2(lp0*log2e + log2_pi)
    float4 e4A = *(const float4*)(st[0] + (2 * l) * STRIDE);
    float4 e4B = *(const float4*)(st[0] + (2 * l + 1) * STRIDE);
    float qAf = ex2f(fmaf(e4A.x, L2E, lpiA));
    float qBf = ex2f(fmaf(e4B.x, L2E, lpiB));
    q0[l] = pack_bf16x2(qAf, qBf);

    double cacc = 0.0;
    float  gp   = 0.0f;

    // t = 1, 2, 3
    step(q0, q1, l, Ta, Tb, e4A.y, e4B.y, 0.f, qAf, qBf);
    step(q1, q0, l, Ta, Tb, e4A.z, e4B.z, 0.f, qAf, qBf);
    step(q0, q1, l, Ta, Tb, e4A.w, e4B.w, 0.f, qAf, qBf);

#pragma unroll 1
    for (int t0 = 4; t0 < NSs; t0 += 4) {
        if ((t0 & 31) == 0) {
            wait_group<0>();
            __syncwarp();
            if (t0 + 32 < NSs)
                issue_stage(st[((t0 >> 5) + 1) & 1], base + t0 + 32, l);
        }
        const float* sb = st[(t0 >> 5) & 1];
        const int tt = t0 & 31;
        float4 eA = *(const float4*)(sb + (2 * l) * STRIDE + tt);
        float4 eB = *(const float4*)(sb + (2 * l + 1) * STRIDE + tt);

        step(q1, q0, l, Ta, Tb, eA.x, eB.x, gp,  qAf, qBf);
        step(q0, q1, l, Ta, Tb, eA.y, eB.y, 0.f, qAf, qBf);
        step(q1, q0, l, Ta, Tb, eA.z, eB.z, 0.f, qAf, qBf);
        step(q0, q1, l, Ta, Tb, eA.w, eB.w, 0.f, qAf, qBf);
        gp = 0.0f;

        if ((t0 & 15) == 4) {                  // renorm every 16 steps
            float S = warp_sum(qAf + qBf);
            float g = lg2f(S);
            cacc += (double)g;
            gp = -g;                           // folded into next step's ex2
        }
    }

    float S = warp_sum(qAf + qBf);
    if (l == 0) gPart[b] = LN2 * (float)(cacc + (double)lg2f(S));
}

// ---------------------------------------------------------------------------
// deterministic final reduction
// ---------------------------------------------------------------------------
__global__ void reduce_kernel(float* __restrict__ out) {
    __shared__ double s[256];
    int t = threadIdx.x;
    double v = 0.0;
    for (int i = t; i < Bseq; i += 256) v += (double)gPart[i];
    s[t] = v;
    __syncthreads();
    for (int o = 128; o > 0; o >>= 1) {
        if (t < o) s[t] += s[t + o];
        __syncthreads();
    }
    if (t == 0) out[0] = (float)s[0];
}

// ---------------------------------------------------------------------------
extern "C" void kernel_launch(void* const* d_in, const int* in_sizes, int n_in,
                              void* d_out, int out_size) {
    const float* lp = (const float*)d_in[0];
    const float* pi = (const float*)d_in[1];
    const float* T  = (const float*)d_in[2];
    (void)in_sizes; (void)n_in; (void)out_size;

    prep_kernel<<<2, 1024>>>(pi, T);
    pack_kernel<<<Kdim, 32>>>();
    fwd_kernel<<<Bseq, 32>>>(lp);
    reduce_kernel<<<1, 256>>>((float*)d_out);
}